// round 11
// baseline (speedup 1.0000x reference)
#include <cuda_runtime.h>
#include <cuda_bf16.h>

// Problem constants
#define BATCH 4096
#define SEQ   512
#define HID   32
// NB = 1: one batch element per warp; 4096 one-warp blocks -> 6.92 warps/SMSP

using u64 = unsigned long long;

// ---- packed f32x2 helpers (FFMA2 path, PTX-only) ----
__device__ __forceinline__ u64 pack2(float lo, float hi) {
    u64 r; asm("mov.b64 %0, {%1, %2};" : "=l"(r) : "f"(lo), "f"(hi)); return r;
}
__device__ __forceinline__ void unpack2(u64 v, float& lo, float& hi) {
    asm("mov.b64 {%0, %1}, %2;" : "=f"(lo), "=f"(hi) : "l"(v));
}
__device__ __forceinline__ u64 fma2(u64 a, u64 b, u64 c) {
    u64 d; asm("fma.rn.f32x2 %0, %1, %2, %3;" : "=l"(d) : "l"(a), "l"(b), "l"(c)); return d;
}
__device__ __forceinline__ u64 add2(u64 a, u64 b) {
    u64 d; asm("add.rn.f32x2 %0, %1, %2;" : "=l"(d) : "l"(a), "l"(b)); return d;
}
__device__ __forceinline__ float lo2(u64 v) {
    float lo, hi; unpack2(v, lo, hi); return lo;
}

// ---- hardware tanh (MUFU.TANH, sm_75+) ----
__device__ __forceinline__ float tanh_hw(float v) {
    float r; asm("tanh.approx.f32 %0, %1;" : "=f"(r) : "f"(v)); return r;
}
// preactivation already halved (0.5 folded into weights): sigmoid(a), in = a/2
__device__ __forceinline__ float sig_h(float half_a) {
    return fmaf(0.5f, tanh_hw(half_a), 0.5f);
}

// ---- exact-path activations for the tail section (unchanged precision) ----
__device__ __forceinline__ float sigf(float v) {
    return __fdividef(1.0f, 1.0f + __expf(-v));
}
__device__ __forceinline__ float tanhf_fast(float v) {
    return __fdividef(2.0f, 1.0f + __expf(-2.0f * v)) - 1.0f;
}

// ---------------------------------------------------------------------------
// Single fused kernel, NB=1: 4096 one-warp blocks (one batch element each).
// Lane = hidden unit j. All Whh1 weights in registers (64 u64 pairs / lane),
// scaled so i,f,o gates produce a/2 (0.5*tanh(a/2)+0.5 sigmoid form) and g
// produces a. h travels through a 512-byte double-buffered smem stage as
// duplicated f32 pairs -> hot loop is 32x (broadcast LDS.64 + 2 FFMA2).
// Fine warp granularity balances the FFMA2-rt load across SMSPs (binding
// SMSP: 7 warps x 66 FFMA2 x rt3 = 1386 cyc/step vs 1584 at NB=4) and 7
// warps/SMSP hide all latency.
// ---------------------------------------------------------------------------
__global__ void __launch_bounds__(32) lstm_kernel(
    const float* __restrict__ x,
    const float* __restrict__ h0,   const float* __restrict__ c0,
    const float* __restrict__ Wih1, const float* __restrict__ Whh1,
    const float* __restrict__ bih1, const float* __restrict__ bhh1,
    const float* __restrict__ Wih2, const float* __restrict__ Whh2,
    const float* __restrict__ bih2, const float* __restrict__ bhh2,
    const float* __restrict__ Wfc,  const float* __restrict__ bfc,
    float* __restrict__ out)
{
    __shared__ u64 Hs[2][32];            // [buf][k] = (h_k, h_k)

    const int j  = threadIdx.x;          // lane = hidden unit
    const int b  = blockIdx.x;           // batch element

    // ---- inline pack: all 32 k-slices of scaled Whh1 into registers ----
    // i,f,o rows scaled by 0.5 (sigmoid-as-tanh form); g row unscaled.
    u64 wIFr[32], wGOr[32];
    {
        const float4* W1v = reinterpret_cast<const float4*>(Whh1);
        #pragma unroll
        for (int q = 0; q < 8; q++) {
            float4 wi = W1v[(0  + j) * 8 + q];
            float4 wf = W1v[(32 + j) * 8 + q];
            float4 wg = W1v[(64 + j) * 8 + q];
            float4 wo = W1v[(96 + j) * 8 + q];
            wIFr[4 * q + 0] = pack2(0.5f * wi.x, 0.5f * wf.x);
            wIFr[4 * q + 1] = pack2(0.5f * wi.y, 0.5f * wf.y);
            wIFr[4 * q + 2] = pack2(0.5f * wi.z, 0.5f * wf.z);
            wIFr[4 * q + 3] = pack2(0.5f * wi.w, 0.5f * wf.w);
            wGOr[4 * q + 0] = pack2(wg.x, 0.5f * wo.x);
            wGOr[4 * q + 1] = pack2(wg.y, 0.5f * wo.y);
            wGOr[4 * q + 2] = pack2(wg.z, 0.5f * wo.z);
            wGOr[4 * q + 3] = pack2(wg.w, 0.5f * wo.w);
        }
    }

    // Per-lane constants: combined bias and input weight, gate-paired, scaled
    const u64 biasIF = pack2(0.5f * (bih1[0  + j] + bhh1[0  + j]),
                             0.5f * (bih1[32 + j] + bhh1[32 + j]));
    const u64 biasGO = pack2(       (bih1[64 + j] + bhh1[64 + j]),
                             0.5f * (bih1[96 + j] + bhh1[96 + j]));
    const u64 wihIF  = pack2(0.5f * Wih1[0  + j],
                             0.5f * Wih1[32 + j]);
    const u64 wihGO  = pack2(       Wih1[64 + j],
                             0.5f * Wih1[96 + j]);

    // Carry c in a register; h lives in the smem stage
    float c = c0[b * HID + j];
    {
        float h = h0[b * HID + j];
        Hs[0][j] = pack2(h, h);
    }

    // x[t][b]: all lanes load the same address (broadcast). Prefetch 1 ahead.
    float xc = x[b];
    __syncwarp();

    // ---------------- 512-step recurrence ----------------
    #pragma unroll 1
    for (int t = 0; t < SEQ; t++) {
        const int rb = t & 1;

        float xn = 0.0f;
        if (t + 1 < SEQ) xn = x[(t + 1) * BATCH + b];

        // Two accumulator pairs per gate group (even/odd k) to halve the
        // dependent-FMA chain; combined at the end.
        u64 xd = pack2(xc, xc);
        u64 aIF0 = fma2(xd, wihIF, biasIF);
        u64 aGO0 = fma2(xd, wihGO, biasGO);
        u64 aIF1 = 0ull;
        u64 aGO1 = 0ull;

        #pragma unroll
        for (int k = 0; k < 32; k += 2) {
            u64 hq0 = Hs[rb][k];           // broadcast LDS.64, pre-paired
            u64 hq1 = Hs[rb][k + 1];
            aIF0 = fma2(hq0, wIFr[k],     aIF0);
            aGO0 = fma2(hq0, wGOr[k],     aGO0);
            aIF1 = fma2(hq1, wIFr[k + 1], aIF1);
            aGO1 = fma2(hq1, wGOr[k + 1], aGO1);
        }
        u64 aIF = add2(aIF0, aIF1);
        u64 aGO = add2(aGO0, aGO1);

        float ai, af, ag, ao;
        unpack2(aIF, ai, af);      // ai, af pre-halved
        unpack2(aGO, ag, ao);      // ag full, ao pre-halved
        float ig = sig_h(ai);
        float fg = sig_h(af);
        float gg = tanh_hw(ag);
        float og = sig_h(ao);
        c = fmaf(fg, c, ig * gg);
        float hn = og * tanh_hw(c);

        Hs[rb ^ 1][j] = pack2(hn, hn);
        xc = xn;
        __syncwarp();
    }

    // ---------------- inline tail: cell 2 + FC (exact path) ----------------
    // SEQ even -> final h is in Hs[0]; c holds the final cell state.
    float a2i, a2f, a2g, a2o;
    a2i = bih2[0  + j] + bhh2[0  + j];
    a2f = bih2[32 + j] + bhh2[32 + j];
    a2g = bih2[64 + j] + bhh2[64 + j];
    a2o = bih2[96 + j] + bhh2[96 + j];
    {
        const float4* Wi2v = reinterpret_cast<const float4*>(Wih2);
        const float4* Wh2v = reinterpret_cast<const float4*>(Whh2);
        #pragma unroll
        for (int q = 0; q < 8; q++) {
            float4 wi = Wi2v[(0  + j) * 8 + q], hi_ = Wh2v[(0  + j) * 8 + q];
            float4 wf = Wi2v[(32 + j) * 8 + q], hf_ = Wh2v[(32 + j) * 8 + q];
            float4 wg = Wi2v[(64 + j) * 8 + q], hg_ = Wh2v[(64 + j) * 8 + q];
            float4 wo = Wi2v[(96 + j) * 8 + q], ho_ = Wh2v[(96 + j) * 8 + q];
            float ci2[4] = { wi.x + hi_.x, wi.y + hi_.y, wi.z + hi_.z, wi.w + hi_.w };
            float cf2[4] = { wf.x + hf_.x, wf.y + hf_.y, wf.z + hf_.z, wf.w + hf_.w };
            float cg2[4] = { wg.x + hg_.x, wg.y + hg_.y, wg.z + hg_.z, wg.w + hg_.w };
            float co2[4] = { wo.x + ho_.x, wo.y + ho_.y, wo.z + ho_.z, wo.w + ho_.w };
            #pragma unroll
            for (int kk = 0; kk < 4; kk++) {
                int k = 4 * q + kk;
                float hk = lo2(Hs[0][k]);
                a2i = fmaf(hk, ci2[kk], a2i);
                a2f = fmaf(hk, cf2[kk], a2f);
                a2g = fmaf(hk, cg2[kk], a2g);
                a2o = fmaf(hk, co2[kk], a2o);
            }
        }
    }

    float cn  = fmaf(sigf(a2f), c, sigf(a2i) * tanhf_fast(a2g));
    float h1f = sigf(a2o) * tanhf_fast(cn);
    float v = h1f * Wfc[j];
    #pragma unroll
    for (int m = 16; m > 0; m >>= 1)
        v += __shfl_xor_sync(0xffffffffu, v, m);
    if (j == 0) out[b] = v + bfc[0];
}

// ---------------------------------------------------------------------------
// kernel_launch: single fused launch (graph-capturable)
// Input order: x,h0,c0,h1,c1,Wih1,Whh1,bih1,bhh1,Wih2,Whh2,bih2,bhh2,Wfc,bfc
// ---------------------------------------------------------------------------
extern "C" void kernel_launch(void* const* d_in, const int* in_sizes, int n_in,
                              void* d_out, int out_size)
{
    const float* x    = (const float*)d_in[0];
    const float* h0   = (const float*)d_in[1];
    const float* c0   = (const float*)d_in[2];
    const float* Wih1 = (const float*)d_in[5];
    const float* Whh1 = (const float*)d_in[6];
    const float* bih1 = (const float*)d_in[7];
    const float* bhh1 = (const float*)d_in[8];
    const float* Wih2 = (const float*)d_in[9];
    const float* Whh2 = (const float*)d_in[10];
    const float* bih2 = (const float*)d_in[11];
    const float* bhh2 = (const float*)d_in[12];
    const float* Wfc  = (const float*)d_in[13];
    const float* bfc  = (const float*)d_in[14];
    float* out = (float*)d_out;

    lstm_kernel<<<BATCH, 32>>>(x, h0, c0, Wih1, Whh1, bih1, bhh1,
                               Wih2, Whh2, bih2, bhh2, Wfc, bfc, out);
}

// round 13
// speedup vs baseline: 1.3157x; 1.3157x over previous
#include <cuda_runtime.h>
#include <cuda_bf16.h>

// Problem constants
#define BATCH 4096
#define SEQ   512
#define HID   32
#define NB    4            // batch elements per warp; 1024 one-warp blocks

using u64 = unsigned long long;

// ---- packed f32x2 helpers (FFMA2 path, PTX-only) ----
__device__ __forceinline__ u64 pack2(float lo, float hi) {
    u64 r; asm("mov.b64 %0, {%1, %2};" : "=l"(r) : "f"(lo), "f"(hi)); return r;
}
__device__ __forceinline__ void unpack2(u64 v, float& lo, float& hi) {
    asm("mov.b64 {%0, %1}, %2;" : "=f"(lo), "=f"(hi) : "l"(v));
}
__device__ __forceinline__ u64 fma2(u64 a, u64 b, u64 c) {
    u64 d; asm("fma.rn.f32x2 %0, %1, %2, %3;" : "=l"(d) : "l"(a), "l"(b), "l"(c)); return d;
}
__device__ __forceinline__ float lo2(u64 v) {
    float lo, hi; unpack2(v, lo, hi); return lo;
}

// ---- hardware tanh (MUFU.TANH, sm_75+) ----
__device__ __forceinline__ float tanh_hw(float v) {
    float r; asm("tanh.approx.f32 %0, %1;" : "=f"(r) : "f"(v)); return r;
}

// ---- exact-path activations for the tail section (unchanged precision) ----
__device__ __forceinline__ float sigf(float v) {
    return __fdividef(1.0f, 1.0f + __expf(-v));
}
__device__ __forceinline__ float tanhf_fast(float v) {
    return __fdividef(2.0f, 1.0f + __expf(-2.0f * v)) - 1.0f;
}

// ---------------------------------------------------------------------------
// Single fused kernel: inline weight pack -> 512-step scan -> cell2 + FC.
// 1024 one-warp blocks; lane = hidden unit j; NB=4 batches per warp.
// All Whh1 weights in registers (64 u64 pairs / lane), scaled so i,f,o gates
// produce a/2 (0.5*tanh(a/2)+0.5 sigmoid form) and g produces a. The k-loop
// software-pipelines the broadcast h loads one iteration ahead so the 29-cyc
// LDS latency is covered by FFMA2 issue instead of stalling.
// ---------------------------------------------------------------------------
__global__ void __launch_bounds__(32) lstm_kernel(
    const float* __restrict__ x,
    const float* __restrict__ h0,   const float* __restrict__ c0,
    const float* __restrict__ Wih1, const float* __restrict__ Whh1,
    const float* __restrict__ bih1, const float* __restrict__ bhh1,
    const float* __restrict__ Wih2, const float* __restrict__ Whh2,
    const float* __restrict__ bih2, const float* __restrict__ bhh2,
    const float* __restrict__ Wfc,  const float* __restrict__ bfc,
    float* __restrict__ out)
{
    __shared__ ulonglong2 Hs[2][NB / 2][32];   // [buf][pair][k] = ((hA,hA),(hB,hB))

    const int j  = threadIdx.x;          // lane = hidden unit
    const int b0 = blockIdx.x * NB;

    // ---- inline pack: all 32 k-slices of scaled Whh1 into registers ----
    // i,f,o rows scaled by 0.5 (sigmoid-as-tanh form); g row unscaled.
    u64 wIFr[32], wGOr[32];
    {
        const float4* W1v = reinterpret_cast<const float4*>(Whh1);
        #pragma unroll
        for (int q = 0; q < 8; q++) {
            float4 wi = W1v[(0  + j) * 8 + q];
            float4 wf = W1v[(32 + j) * 8 + q];
            float4 wg = W1v[(64 + j) * 8 + q];
            float4 wo = W1v[(96 + j) * 8 + q];
            wIFr[4 * q + 0] = pack2(0.5f * wi.x, 0.5f * wf.x);
            wIFr[4 * q + 1] = pack2(0.5f * wi.y, 0.5f * wf.y);
            wIFr[4 * q + 2] = pack2(0.5f * wi.z, 0.5f * wf.z);
            wIFr[4 * q + 3] = pack2(0.5f * wi.w, 0.5f * wf.w);
            wGOr[4 * q + 0] = pack2(wg.x, 0.5f * wo.x);
            wGOr[4 * q + 1] = pack2(wg.y, 0.5f * wo.y);
            wGOr[4 * q + 2] = pack2(wg.z, 0.5f * wo.z);
            wGOr[4 * q + 3] = pack2(wg.w, 0.5f * wo.w);
        }
    }

    // Per-lane constants: combined bias and input weight, gate-paired, scaled
    const u64 biasIF = pack2(0.5f * (bih1[0  + j] + bhh1[0  + j]),
                             0.5f * (bih1[32 + j] + bhh1[32 + j]));
    const u64 biasGO = pack2(       (bih1[64 + j] + bhh1[64 + j]),
                             0.5f * (bih1[96 + j] + bhh1[96 + j]));
    const u64 wihIF  = pack2(0.5f * Wih1[0  + j],
                             0.5f * Wih1[32 + j]);
    const u64 wihGO  = pack2(       Wih1[64 + j],
                             0.5f * Wih1[96 + j]);

    // Carry c in registers; h lives in the smem stage
    float c[NB];
    #pragma unroll
    for (int b = 0; b < NB; b++) c[b] = c0[(b0 + b) * HID + j];

    #pragma unroll
    for (int g = 0; g < NB / 2; g++) {
        float ha = h0[(b0 + 2 * g)     * HID + j];
        float hb = h0[(b0 + 2 * g + 1) * HID + j];
        ulonglong2 hq;
        hq.x = pack2(ha, ha);
        hq.y = pack2(hb, hb);
        Hs[0][g][j] = hq;
    }

    // x[t][b0..b0+3] contiguous: uniform LDG.128 broadcast; prefetch 1 ahead
    float4 xc = *reinterpret_cast<const float4*>(&x[b0]);
    __syncwarp();

    // ---------------- 512-step recurrence ----------------
    #pragma unroll 1
    for (int t = 0; t < SEQ; t++) {
        const int rb = t & 1;

        // branchless next-x prefetch (last step re-reads current row)
        const int tn = (t + 1 < SEQ) ? (t + 1) : t;
        float4 xn = *reinterpret_cast<const float4*>(&x[tn * BATCH + b0]);

        u64 aIF[NB], aGO[NB];
        {
            u64 xd0 = pack2(xc.x, xc.x);
            u64 xd1 = pack2(xc.y, xc.y);
            u64 xd2 = pack2(xc.z, xc.z);
            u64 xd3 = pack2(xc.w, xc.w);
            aIF[0] = fma2(xd0, wihIF, biasIF);  aGO[0] = fma2(xd0, wihGO, biasGO);
            aIF[1] = fma2(xd1, wihIF, biasIF);  aGO[1] = fma2(xd1, wihGO, biasGO);
            aIF[2] = fma2(xd2, wihIF, biasIF);  aGO[2] = fma2(xd2, wihGO, biasGO);
            aIF[3] = fma2(xd3, wihIF, biasIF);  aGO[3] = fma2(xd3, wihGO, biasGO);
        }

        // recurrent matvec with distance-1 software pipeline on the h loads:
        // load Hs[k+1] before issuing k's 8 FFMA2s.
        {
            ulonglong2 cur0 = Hs[rb][0][0];
            ulonglong2 cur1 = Hs[rb][1][0];
            #pragma unroll
            for (int k = 0; k < 32; k++) {
                ulonglong2 nxt0, nxt1;
                if (k < 31) {
                    nxt0 = Hs[rb][0][k + 1];
                    nxt1 = Hs[rb][1][k + 1];
                }
                u64 wIF = wIFr[k];
                u64 wGO = wGOr[k];
                aIF[0] = fma2(cur0.x, wIF, aIF[0]);
                aGO[0] = fma2(cur0.x, wGO, aGO[0]);
                aIF[1] = fma2(cur0.y, wIF, aIF[1]);
                aGO[1] = fma2(cur0.y, wGO, aGO[1]);
                aIF[2] = fma2(cur1.x, wIF, aIF[2]);
                aGO[2] = fma2(cur1.x, wGO, aGO[2]);
                aIF[3] = fma2(cur1.y, wIF, aIF[3]);
                aGO[3] = fma2(cur1.y, wGO, aGO[3]);
                if (k < 31) {
                    cur0 = nxt0;
                    cur1 = nxt1;
                }
            }
        }

        // ---- gate-major epilogue: all 16 gate MUFUs issued together ----
        float ai[NB], af[NB], ag[NB], ao[NB];
        #pragma unroll
        for (int b = 0; b < NB; b++) {
            unpack2(aIF[b], ai[b], af[b]);   // pre-halved
            unpack2(aGO[b], ag[b], ao[b]);   // ag full, ao pre-halved
        }
        float tg[NB], ti[NB], tf_[NB], to_[NB];
        #pragma unroll
        for (int b = 0; b < NB; b++) tg[b]  = tanh_hw(ag[b]);
        #pragma unroll
        for (int b = 0; b < NB; b++) ti[b]  = tanh_hw(ai[b]);
        #pragma unroll
        for (int b = 0; b < NB; b++) tf_[b] = tanh_hw(af[b]);
        #pragma unroll
        for (int b = 0; b < NB; b++) to_[b] = tanh_hw(ao[b]);

        float hn[NB];
        #pragma unroll
        for (int b = 0; b < NB; b++) {
            float ig = fmaf(0.5f, ti[b],  0.5f);
            float fg = fmaf(0.5f, tf_[b], 0.5f);
            float og = fmaf(0.5f, to_[b], 0.5f);
            c[b]  = fmaf(fg, c[b], ig * tg[b]);
            hn[b] = og * tanh_hw(c[b]);
        }

        #pragma unroll
        for (int g = 0; g < NB / 2; g++) {
            ulonglong2 hq;
            hq.x = pack2(hn[2 * g],     hn[2 * g]);
            hq.y = pack2(hn[2 * g + 1], hn[2 * g + 1]);
            Hs[rb ^ 1][g][j] = hq;
        }
        xc = xn;
        __syncwarp();
    }

    // ---------------- inline tail: cell 2 + FC (exact path) ----------------
    // SEQ even -> final h is in Hs[0]; c[] holds final cell state.
    float a2i[NB], a2f[NB], a2g[NB], a2o[NB];
    {
        float bi2 = bih2[0  + j] + bhh2[0  + j];
        float bf2 = bih2[32 + j] + bhh2[32 + j];
        float bg2 = bih2[64 + j] + bhh2[64 + j];
        float bo2 = bih2[96 + j] + bhh2[96 + j];
        #pragma unroll
        for (int b = 0; b < NB; b++) {
            a2i[b] = bi2; a2f[b] = bf2; a2g[b] = bg2; a2o[b] = bo2;
        }
    }
    {
        const float4* Wi2v = reinterpret_cast<const float4*>(Wih2);
        const float4* Wh2v = reinterpret_cast<const float4*>(Whh2);
        #pragma unroll
        for (int q = 0; q < 8; q++) {
            float4 wi = Wi2v[(0  + j) * 8 + q], hi_ = Wh2v[(0  + j) * 8 + q];
            float4 wf = Wi2v[(32 + j) * 8 + q], hf_ = Wh2v[(32 + j) * 8 + q];
            float4 wg = Wi2v[(64 + j) * 8 + q], hg_ = Wh2v[(64 + j) * 8 + q];
            float4 wo = Wi2v[(96 + j) * 8 + q], ho_ = Wh2v[(96 + j) * 8 + q];
            float ci2[4] = { wi.x + hi_.x, wi.y + hi_.y, wi.z + hi_.z, wi.w + hi_.w };
            float cf2[4] = { wf.x + hf_.x, wf.y + hf_.y, wf.z + hf_.z, wf.w + hf_.w };
            float cg2[4] = { wg.x + hg_.x, wg.y + hg_.y, wg.z + hg_.z, wg.w + hg_.w };
            float co2[4] = { wo.x + ho_.x, wo.y + ho_.y, wo.z + ho_.z, wo.w + ho_.w };
            #pragma unroll
            for (int kk = 0; kk < 4; kk++) {
                int k = 4 * q + kk;
                ulonglong2 hq0 = Hs[0][0][k];
                ulonglong2 hq1 = Hs[0][1][k];
                float hk[NB] = { lo2(hq0.x), lo2(hq0.y), lo2(hq1.x), lo2(hq1.y) };
                #pragma unroll
                for (int b = 0; b < NB; b++) {
                    a2i[b] = fmaf(hk[b], ci2[kk], a2i[b]);
                    a2f[b] = fmaf(hk[b], cf2[kk], a2f[b]);
                    a2g[b] = fmaf(hk[b], cg2[kk], a2g[b]);
                    a2o[b] = fmaf(hk[b], co2[kk], a2o[b]);
                }
            }
        }
    }

    const float wfc_j = Wfc[j];
    const float bfc0  = bfc[0];
    #pragma unroll
    for (int b = 0; b < NB; b++) {
        float cn  = fmaf(sigf(a2f[b]), c[b], sigf(a2i[b]) * tanhf_fast(a2g[b]));
        float h1f = sigf(a2o[b]) * tanhf_fast(cn);
        float v = h1f * wfc_j;
        #pragma unroll
        for (int m = 16; m > 0; m >>= 1)
            v += __shfl_xor_sync(0xffffffffu, v, m);
        if (j == 0) out[b0 + b] = v + bfc0;
    }
}

// ---------------------------------------------------------------------------
// kernel_launch: single fused launch (graph-capturable)
// Input order: x,h0,c0,h1,c1,Wih1,Whh1,bih1,bhh1,Wih2,Whh2,bih2,bhh2,Wfc,bfc
// ---------------------------------------------------------------------------
extern "C" void kernel_launch(void* const* d_in, const int* in_sizes, int n_in,
                              void* d_out, int out_size)
{
    const float* x    = (const float*)d_in[0];
    const float* h0   = (const float*)d_in[1];
    const float* c0   = (const float*)d_in[2];
    const float* Wih1 = (const float*)d_in[5];
    const float* Whh1 = (const float*)d_in[6];
    const float* bih1 = (const float*)d_in[7];
    const float* bhh1 = (const float*)d_in[8];
    const float* Wih2 = (const float*)d_in[9];
    const float* Whh2 = (const float*)d_in[10];
    const float* bih2 = (const float*)d_in[11];
    const float* bhh2 = (const float*)d_in[12];
    const float* Wfc  = (const float*)d_in[13];
    const float* bfc  = (const float*)d_in[14];
    float* out = (float*)d_out;

    lstm_kernel<<<BATCH / NB, 32>>>(x, h0, c0, Wih1, Whh1, bih1, bhh1,
                                    Wih2, Whh2, bih2, bhh2, Wfc, bfc, out);
}